// round 2
// baseline (speedup 1.0000x reference)
#include <cuda_runtime.h>

#define M_PILLARS 16384
#define N_POINTS  4096
#define C_FEAT    64
#define RADIUS2   1.0f
#define VX        0.16f
#define VY        0.16f
#define PCX       0.0f
#define PCY       -25.6f

__global__ __launch_bounds__(256)
void query_fusion_kernel(const float* __restrict__ pillar_feature,
                         const int*   __restrict__ coors,
                         const float* __restrict__ seg_feats,
                         const float* __restrict__ seg_points,
                         float*       __restrict__ out) {
    __shared__ float2 pts[N_POINTS];   // 32 KB

    const int tid = threadIdx.x;
    // Stage point xy into shared (coalesced-ish: 3-stride source)
    for (int i = tid; i < N_POINTS; i += blockDim.x) {
        pts[i] = make_float2(seg_points[i * 3 + 0], seg_points[i * 3 + 1]);
    }
    __syncthreads();

    const int warp = tid >> 5;
    const int lane = tid & 31;
    const int m = blockIdx.x * (blockDim.x >> 5) + warp;
    if (m >= M_PILLARS) return;

    // Pillar center xy from coors row [0,0,y,x]
    const float px = ((float)coors[m * 4 + 3] + 0.5f) * VX + PCX;
    const float py = ((float)coors[m * 4 + 2] + 0.5f) * VY + PCY;

    // Ordered ball query: first 4 in-radius indices (scan order)
    int i0 = 0, i1 = 0, i2 = 0, i3 = 0;
    int found = 0;

    for (int base = 0; base < N_POINTS; base += 32) {
        float2 p = pts[base + lane];
        float dx = px - p.x;
        float dy = py - p.y;
        bool within = (dx * dx + dy * dy) < RADIUS2;
        unsigned mask = __ballot_sync(0xffffffffu, within);
        // mask is uniform across the warp; extraction loop is warp-uniform.
        while (mask) {
            int b = base + (__ffs(mask) - 1);
            mask &= (mask - 1);
            if      (found == 0) i0 = b;
            else if (found == 1) i1 = b;
            else if (found == 2) i2 = b;
            else                 i3 = b;
            found++;
            if (found == 4) break;
        }
        if (found == 4) break;
    }

    // Pad with first found index (all-zero if none found)
    if (found == 0) { i0 = i1 = i2 = i3 = 0; }
    else {
        if (found < 2) i1 = i0;
        if (found < 3) i2 = i0;
        if (found < 4) i3 = i0;
    }

    // Reference quirk: flag = (sum of indices) > 0
    const bool flag = (i0 + i1 + i2 + i3) > 0;

    // Feature fuse: 64 channels, 2 per lane, coalesced
    const size_t mrow = (size_t)m * C_FEAT;
    float v0 = pillar_feature[mrow + lane];
    float v1 = pillar_feature[mrow + lane + 32];

    if (flag) {
        const size_t r0 = (size_t)i0 * C_FEAT;
        const size_t r1 = (size_t)i1 * C_FEAT;
        const size_t r2 = (size_t)i2 * C_FEAT;
        const size_t r3 = (size_t)i3 * C_FEAT;

        float a0 = seg_feats[r0 + lane];
        float a1 = seg_feats[r1 + lane];
        float a2 = seg_feats[r2 + lane];
        float a3 = seg_feats[r3 + lane];
        float b0 = seg_feats[r0 + lane + 32];
        float b1 = seg_feats[r1 + lane + 32];
        float b2 = seg_feats[r2 + lane + 32];
        float b3 = seg_feats[r3 + lane + 32];

        v0 += fmaxf(fmaxf(a0, a1), fmaxf(a2, a3));
        v1 += fmaxf(fmaxf(b0, b1), fmaxf(b2, b3));
    }

    out[mrow + lane]      = v0;
    out[mrow + lane + 32] = v1;
}

extern "C" void kernel_launch(void* const* d_in, const int* in_sizes, int n_in,
                              void* d_out, int out_size) {
    const float* pillar_feature = (const float*)d_in[0];  // [M, 64]
    const int*   coors          = (const int*)  d_in[1];  // [M, 4]
    const float* seg_feats      = (const float*)d_in[2];  // [N, 64]
    const float* seg_points     = (const float*)d_in[3];  // [N, 3]
    float* out = (float*)d_out;                            // [M, 64]

    const int warps_per_block = 8;          // 256 threads
    const int blocks = M_PILLARS / warps_per_block;  // 2048
    query_fusion_kernel<<<blocks, 256>>>(pillar_feature, coors, seg_feats,
                                         seg_points, out);
}

// round 3
// speedup vs baseline: 2.0916x; 2.0916x over previous
#include <cuda_runtime.h>

#define M_PILLARS 16384
#define N_POINTS  4096
#define C_FEAT    64
#define RADIUS2   1.0f
#define VX        0.16f
#define VY        0.16f
#define PCY      -25.6f

#define GW        52            // grid cells per dim (cell size = 1.0 = R)
#define NCELLS    (GW * GW)     // 2704
#define SENT      0x7fffffffu

__device__ int    g_bin_count[NCELLS];
__device__ int    g_bin_start[NCELLS + 1];
__device__ int    g_cursor[NCELLS];
__device__ float2 g_sorted_xy[N_POINTS];
__device__ int    g_sorted_idx[N_POINTS];

__device__ __forceinline__ int cell_of(float x, float y) {
    int gx = (int)floorf(x);            // cell size 1.0, x in [0, 51.2)
    int gy = (int)floorf(y + 25.6f);    // y in [-25.6, 25.6)
    gx = min(max(gx, 0), GW - 1);
    gy = min(max(gy, 0), GW - 1);
    return gy * GW + gx;
}

__global__ void k_zero() {
    int i = blockIdx.x * blockDim.x + threadIdx.x;
    if (i < NCELLS) g_bin_count[i] = 0;
}

__global__ void k_count(const float* __restrict__ seg_points) {
    int i = blockIdx.x * blockDim.x + threadIdx.x;
    if (i >= N_POINTS) return;
    float x = seg_points[i * 3 + 0];
    float y = seg_points[i * 3 + 1];
    atomicAdd(&g_bin_count[cell_of(x, y)], 1);
}

__global__ __launch_bounds__(1024) void k_scan() {
    __shared__ int sh[4096];
    int t = threadIdx.x;
    for (int i = t; i < 4096; i += 1024) sh[i] = (i < NCELLS) ? g_bin_count[i] : 0;
    __syncthreads();
    for (int off = 1; off < 4096; off <<= 1) {
        int v[4];
        #pragma unroll
        for (int k = 0; k < 4; k++) {
            int i = t + k * 1024;
            v[k] = (i >= off) ? sh[i - off] : 0;
        }
        __syncthreads();
        #pragma unroll
        for (int k = 0; k < 4; k++) sh[t + k * 1024] += v[k];
        __syncthreads();
    }
    // sh = inclusive scan; emit exclusive
    for (int i = t; i <= NCELLS; i += 1024) {
        int ex = (i == 0) ? 0 : sh[i - 1];
        g_bin_start[i] = ex;
        if (i < NCELLS) g_cursor[i] = ex;
    }
}

__global__ void k_scatter(const float* __restrict__ seg_points) {
    int i = blockIdx.x * blockDim.x + threadIdx.x;
    if (i >= N_POINTS) return;
    float x = seg_points[i * 3 + 0];
    float y = seg_points[i * 3 + 1];
    int pos = atomicAdd(&g_cursor[cell_of(x, y)], 1);
    g_sorted_xy[pos]  = make_float2(x, y);
    g_sorted_idx[pos] = i;
}

__global__ __launch_bounds__(256)
void k_query_fuse(const float* __restrict__ pillar_feature,
                  const int*   __restrict__ coors,
                  const float* __restrict__ seg_feats,
                  float*       __restrict__ out) {
    const int warp = threadIdx.x >> 5;
    const int lane = threadIdx.x & 31;
    const int m = blockIdx.x * (blockDim.x >> 5) + warp;
    if (m >= M_PILLARS) return;

    const float px = ((float)coors[m * 4 + 3] + 0.5f) * VX;
    const float py = ((float)coors[m * 4 + 2] + 0.5f) * VY + PCY;

    // 3x3 cell neighborhood (cell size == R)
    const int cx = min(max((int)floorf(px), 0), GW - 1);
    const int cy = min(max((int)floorf(py + 25.6f), 0), GW - 1);
    const int cx0 = max(cx - 1, 0), cx1 = min(cx + 1, GW - 1);
    const int cy0 = max(cy - 1, 0), cy1 = min(cy + 1, GW - 1);

    // Per-lane 4 smallest in-radius original indices (sorted ascending)
    unsigned c0 = SENT, c1 = SENT, c2 = SENT, c3 = SENT;

    for (int gy = cy0; gy <= cy1; gy++) {
        const int s = g_bin_start[gy * GW + cx0];
        const int e = g_bin_start[gy * GW + cx1 + 1];
        for (int j = s + lane; j < e; j += 32) {
            float2 p = g_sorted_xy[j];
            float dx = px - p.x;
            float dy = py - p.y;
            if (dx * dx + dy * dy < RADIUS2) {
                unsigned v = (unsigned)g_sorted_idx[j];
                if (v < c3) {
                    c3 = v;
                    unsigned t;
                    if (c3 < c2) { t = c2; c2 = c3; c3 = t; }
                    if (c2 < c1) { t = c1; c1 = c2; c2 = t; }
                    if (c1 < c0) { t = c0; c0 = c1; c1 = t; }
                }
            }
        }
    }

    // Warp-select the 4 globally smallest indices
    int i0 = 0, i1 = 0, i2 = 0, i3 = 0;
    int found = 0;
    #pragma unroll
    for (int r = 0; r < 4; r++) {
        unsigned mn = __reduce_min_sync(0xffffffffu, c0);
        if (mn == SENT) break;          // uniform branch
        if (c0 == mn) { c0 = c1; c1 = c2; c2 = c3; c3 = SENT; }
        if      (r == 0) i0 = (int)mn;
        else if (r == 1) i1 = (int)mn;
        else if (r == 2) i2 = (int)mn;
        else             i3 = (int)mn;
        found = r + 1;
    }

    if (found == 0) { i0 = i1 = i2 = i3 = 0; }
    else {
        if (found < 2) i1 = i0;
        if (found < 3) i2 = i0;
        if (found < 4) i3 = i0;
    }

    // Reference quirk: flag = (sum of indices) > 0
    const bool flag = (i0 + i1 + i2 + i3) > 0;

    const size_t mrow = (size_t)m * C_FEAT;
    float v0 = pillar_feature[mrow + lane];
    float v1 = pillar_feature[mrow + lane + 32];

    if (flag) {
        const size_t r0 = (size_t)i0 * C_FEAT;
        const size_t r1 = (size_t)i1 * C_FEAT;
        const size_t r2 = (size_t)i2 * C_FEAT;
        const size_t r3 = (size_t)i3 * C_FEAT;

        float a0 = seg_feats[r0 + lane];
        float a1 = seg_feats[r1 + lane];
        float a2 = seg_feats[r2 + lane];
        float a3 = seg_feats[r3 + lane];
        float b0 = seg_feats[r0 + lane + 32];
        float b1 = seg_feats[r1 + lane + 32];
        float b2 = seg_feats[r2 + lane + 32];
        float b3 = seg_feats[r3 + lane + 32];

        v0 += fmaxf(fmaxf(a0, a1), fmaxf(a2, a3));
        v1 += fmaxf(fmaxf(b0, b1), fmaxf(b2, b3));
    }

    out[mrow + lane]      = v0;
    out[mrow + lane + 32] = v1;
}

extern "C" void kernel_launch(void* const* d_in, const int* in_sizes, int n_in,
                              void* d_out, int out_size) {
    const float* pillar_feature = (const float*)d_in[0];  // [M, 64]
    const int*   coors          = (const int*)  d_in[1];  // [M, 4]
    const float* seg_feats      = (const float*)d_in[2];  // [N, 64]
    const float* seg_points     = (const float*)d_in[3];  // [N, 3]
    float* out = (float*)d_out;                            // [M, 64]

    k_zero<<<(NCELLS + 255) / 256, 256>>>();
    k_count<<<N_POINTS / 256, 256>>>(seg_points);
    k_scan<<<1, 1024>>>();
    k_scatter<<<N_POINTS / 256, 256>>>(seg_points);
    k_query_fuse<<<M_PILLARS / 8, 256>>>(pillar_feature, coors, seg_feats, out);
}